// round 9
// baseline (speedup 1.0000x reference)
#include <cuda_runtime.h>
#include <cstdint>

#define MN       1024
#define BATCH    2048
#define DIM      128
#define NITER_F  100.0f
#define ALPHA_F  0.3f
#define SIGMA_F  16.0f

// ---------------- scratch ----------------
__device__ unsigned long long g_part[8][BATCH];  // per-m-block argmin partials
__device__ float g_S[MN * DIM];
__device__ float g_cnt[MN];

__device__ __forceinline__ unsigned int f2ord(float f) {
    unsigned int u = __float_as_uint(f);
    return (u & 0x80000000u) ? ~u : (u | 0x80000000u);
}

__device__ __forceinline__ void ffma2(unsigned long long& acc,
                                      unsigned long long a,
                                      unsigned long long b) {
    asm("fma.rn.f32x2 %0, %1, %2, %0;" : "+l"(acc) : "l"(a), "l"(b));
}

// ---------------- K1: BMU GEMM + argmin (zeroes scratch, computes w2) ------
// tile 128m x 64b, 256 threads, 8m x 4b per thread, FFMA2 pairs along K.
// 2 CTAs/SM (smem ~104.5KB, <=128 regs) -> 4 warps/SMSP for latency hiding.
// W swizzle key (row>>3)&7 (8-row granule), X key (row>>2)&7 (4-row granule).
__global__ __launch_bounds__(256, 2)
void k_bmu(const float* __restrict__ x, const float* __restrict__ w) {
    extern __shared__ float smem[];
    float* Ws = smem;                                   // 128*128 f = 64KB
    float* Xs = smem + 128 * 128;                       // 64*128 f  = 32KB
    unsigned long long* Red =
        (unsigned long long*)(smem + 128 * 128 + 64 * 128);  // [16][64] = 8KB
    float* w2s = (float*)(Red + 16 * 64);               // [128]

    const int m0 = blockIdx.x * 128;
    const int b0 = blockIdx.y * 64;
    const int tid = threadIdx.x;
    const int wrp = tid >> 5, lane = tid & 31;
    const int ty = (lane >> 2) | ((wrp & 1) << 3);      // 0..15 -> 8 m rows
    const int tx = (lane & 3) | ((wrp >> 1) << 2);      // 0..15 -> 4 b rows

    // fold scratch zeroing into this kernel (256 blocks)
    {
        int z = blockIdx.y * 8 + blockIdx.x;            // 0..255
        if (tid < 128)
            *(float4*)&g_S[z * 512 + tid * 4] = make_float4(0.f, 0.f, 0.f, 0.f);
        if (tid == 255)
            *(float4*)&g_cnt[z * 4] = make_float4(0.f, 0.f, 0.f, 0.f);
    }

    // stage W tile: 128 rows x 32 groups, key (row>>3)&7
    #pragma unroll
    for (int i = 0; i < 16; i++) {
        int idx = tid + i * 256;          // 0..4095
        int row = idx >> 5;
        int g   = idx & 31;
        int sg  = (g ^ ((row >> 3) & 7)) << 2;
        float4 v = *(const float4*)&w[(m0 + row) * DIM + g * 4];
        *(float4*)&Ws[row * 128 + sg] = v;
    }
    // stage X tile: 64 rows x 32 groups, key (row>>2)&7
    #pragma unroll
    for (int i = 0; i < 8; i++) {
        int idx = tid + i * 256;          // 0..2047
        int row = idx >> 5;
        int g   = idx & 31;
        int sg  = (g ^ ((row >> 2) & 7)) << 2;
        float4 u = *(const float4*)&x[(b0 + row) * DIM + g * 4];
        *(float4*)&Xs[row * 128 + sg] = u;
    }
    __syncthreads();

    // w2 from the staged tile (swizzle permutes within the row)
    if (tid < 128) {
        float s = 0.0f;
        #pragma unroll
        for (int g = 0; g < 32; g++) {
            float4 v = *(const float4*)&Ws[tid * 128 + g * 4];
            s += v.x * v.x + v.y * v.y + v.z * v.z + v.w * v.w;
        }
        w2s[tid] = s;
    }

    unsigned long long acc[8][4];
    #pragma unroll
    for (int mi = 0; mi < 8; mi++)
        #pragma unroll
        for (int bj = 0; bj < 4; bj++) acc[mi][bj] = 0ULL;

    const float* wbase = &Ws[(ty * 8) * 128];
    const float* xbase = &Xs[(tx * 4) * 128];
    const int sw = ty & 7;          // W key for rows ty*8..ty*8+7
    const int sx = tx & 7;          // X key for rows tx*4..tx*4+3 ((row>>2)&7)

    #pragma unroll 2
    for (int kt = 0; kt < 32; kt++) {      // 4 k per step
        const int ow = (kt ^ sw) << 2;
        const int ox = (kt ^ sx) << 2;
        ulonglong2 xv[4];
        #pragma unroll
        for (int bj = 0; bj < 4; bj++)
            xv[bj] = *(const ulonglong2*)&xbase[bj * 128 + ox];
        ulonglong2 wv[8];
        #pragma unroll
        for (int mi = 0; mi < 8; mi++)
            wv[mi] = *(const ulonglong2*)&wbase[mi * 128 + ow];
        #pragma unroll
        for (int mi = 0; mi < 8; mi++) {
            #pragma unroll
            for (int bj = 0; bj < 4; bj++) {
                ffma2(acc[mi][bj], wv[mi].x, xv[bj].x);
                ffma2(acc[mi][bj], wv[mi].y, xv[bj].y);
            }
        }
    }
    __syncthreads();   // w2s ready

    float w2r[8];
    #pragma unroll
    for (int mi = 0; mi < 8; mi++) w2r[mi] = w2s[ty * 8 + mi];

    #pragma unroll
    for (int bj = 0; bj < 4; bj++) {
        unsigned long long best = 0xFFFFFFFFFFFFFFFFULL;
        #pragma unroll
        for (int mi = 0; mi < 8; mi++) {
            float lo = __uint_as_float((unsigned int)(acc[mi][bj]));
            float hi = __uint_as_float((unsigned int)(acc[mi][bj] >> 32));
            float d2 = w2r[mi] - 2.0f * (lo + hi);
            unsigned long long key =
                ((unsigned long long)f2ord(d2) << 32) |
                (unsigned long long)(m0 + ty * 8 + mi);
            best = min(best, key);
        }
        Red[ty * 64 + tx * 4 + bj] = best;
    }
    __syncthreads();

    if (tid < 64) {
        unsigned long long best = Red[tid];
        #pragma unroll
        for (int t = 1; t < 16; t++) best = min(best, Red[t * 64 + tid]);
        g_part[blockIdx.x][b0 + tid] = best;   // plain store, no atomics
    }
}

// ---------------- K2: reduce partials + scatter x rows into BMU bins --------
__global__ void k_scatter(const float* __restrict__ x) {
    int warp = (blockIdx.x * blockDim.x + threadIdx.x) >> 5;  // 0..2047
    int lane = threadIdx.x & 31;
    if (warp >= BATCH) return;

    unsigned long long v = (lane < 8) ? g_part[lane][warp]
                                      : 0xFFFFFFFFFFFFFFFFULL;
    #pragma unroll
    for (int o = 4; o >= 1; o >>= 1)
        v = min(v, __shfl_xor_sync(0xffffffffu, v, o));
    v = __shfl_sync(0xffffffffu, v, 0);
    int m = (int)(v & 0xFFFFFFFFULL);

    float4 vv = *(const float4*)&x[warp * DIM + lane * 4];
    float* dst = &g_S[m * DIM + lane * 4];
    asm volatile("red.global.add.v4.f32 [%0], {%1, %2, %3, %4};"
                 :: "l"(dst), "f"(vv.x), "f"(vv.y), "f"(vv.z), "f"(vv.w)
                 : "memory");
    if (lane == 0) atomicAdd(&g_cnt[m], 1.0f);
}

// ---------------- K3: fused separable gaussian contraction + update ---------
// 128 blocks = (cx, d-quarter), 256 threads.
__global__ __launch_bounds__(256)
void k_tail(const float* __restrict__ w,
            const int* __restrict__ it,
            float* __restrict__ out) {
    __shared__ float4 Ts[32][9];     // [by][dq], padded
    __shared__ float tc_s[32];
    __shared__ float e_s[32];

    const int cx = blockIdx.x & 31;
    const int d0 = (blockIdx.x >> 5) * 32;   // d-quarter base
    const int tid = threadIdx.x;

    float lr_decay = 1.0f - (float)it[0] / NITER_F;
    float alpha_op = ALPHA_F * lr_decay;
    float sig = SIGMA_F * lr_decay;
    float inv_s2 = 1.0f / (sig * sig);

    if (tid < 32) e_s[tid] = expf(-(float)(tid * tid) * inv_s2);
    __syncthreads();

    // stage A: Ts[by][d] = sum_bx e(|cx-bx|) * S[by*32+bx][d]
    {
        const int by = tid >> 3;           // 0..31
        const int dq = tid & 7;            // float4 index
        const int d  = d0 + dq * 4;
        float4 a = make_float4(0.f, 0.f, 0.f, 0.f);
        #pragma unroll
        for (int bb = 0; bb < 4; bb++) {
            float4 sv[8];
            #pragma unroll
            for (int j = 0; j < 8; j++)
                sv[j] = *(const float4*)&g_S[(by * 32 + bb * 8 + j) * DIM + d];
            #pragma unroll
            for (int j = 0; j < 8; j++) {
                float e = e_s[abs(cx - (bb * 8 + j))];
                a.x += e * sv[j].x; a.y += e * sv[j].y;
                a.z += e * sv[j].z; a.w += e * sv[j].w;
            }
        }
        Ts[by][dq] = a;
    }
    if (tid < 32) {
        float c = 0.0f;
        #pragma unroll
        for (int bx = 0; bx < 32; bx++)
            c += e_s[abs(cx - bx)] * g_cnt[tid * 32 + bx];
        tc_s[tid] = c;
    }
    __syncthreads();

    // stage B
    {
        const int cy = tid >> 3;
        const int dq = tid & 7;
        const int d  = d0 + dq * 4;
        float4 a = make_float4(0.f, 0.f, 0.f, 0.f);
        float s = 0.0f;
        #pragma unroll
        for (int by = 0; by < 32; by++) {
            float e = e_s[abs(cy - by)];
            float4 t = Ts[by][dq];
            a.x += e * t.x; a.y += e * t.y;
            a.z += e * t.z; a.w += e * t.w;
            s += e * tc_s[by];
        }
        const int c = (cy * 32 + cx) * DIM + d;
        float4 wv = *(const float4*)&w[c];
        float4 o;
        o.x = wv.x + alpha_op * (a.x - s * wv.x);
        o.y = wv.y + alpha_op * (a.y - s * wv.y);
        o.z = wv.z + alpha_op * (a.z - s * wv.z);
        o.w = wv.w + alpha_op * (a.w - s * wv.w);
        *(float4*)&out[c] = o;
    }
}

// ---------------- launch ----------------
extern "C" void kernel_launch(void* const* d_in, const int* in_sizes, int n_in,
                              void* d_out, int out_size) {
    const float* x   = (const float*)d_in[0];   // [2048,128]
    const float* w   = (const float*)d_in[1];   // [1024,128]
    const int*   it  = (const int*)d_in[3];
    float* out = (float*)d_out;

    const int bmu_smem = (128 * 128 + 64 * 128) * 4 + 16 * 64 * 8 + 128 * 4;
    cudaFuncSetAttribute(k_bmu, cudaFuncAttributeMaxDynamicSharedMemorySize,
                         bmu_smem);

    k_bmu<<<dim3(8, 32), 256, bmu_smem>>>(x, w);
    k_scatter<<<256, 256>>>(x);
    k_tail<<<128, 256>>>(w, it, out);
}

// round 10
// speedup vs baseline: 1.0077x; 1.0077x over previous
#include <cuda_runtime.h>
#include <cstdint>

#define MN       1024
#define BATCH    2048
#define DIM      128
#define NITER_F  100.0f
#define ALPHA_F  0.3f
#define SIGMA_F  16.0f

// ---------------- scratch ----------------
__device__ unsigned long long g_part[8][BATCH];  // per-cell-block argmin partials
__device__ float g_S[MN * DIM];
__device__ float g_cnt[MN];

__device__ __forceinline__ unsigned int f2ord(float f) {
    unsigned int u = __float_as_uint(f);
    return (u & 0x80000000u) ? ~u : (u | 0x80000000u);
}

__device__ __forceinline__ float tf32_rna(float v) {
    uint32_t u;
    asm("cvt.rna.tf32.f32 %0, %1;" : "=r"(u) : "f"(v));
    return __uint_as_float(u);
}

__device__ __forceinline__ void mma_tf32(float* d, const uint32_t* a,
                                         uint32_t b0, uint32_t b1) {
    asm volatile(
        "mma.sync.aligned.m16n8k8.row.col.f32.tf32.tf32.f32 "
        "{%0,%1,%2,%3}, {%4,%5,%6,%7}, {%8,%9}, {%0,%1,%2,%3};"
        : "+f"(d[0]), "+f"(d[1]), "+f"(d[2]), "+f"(d[3])
        : "r"(a[0]), "r"(a[1]), "r"(a[2]), "r"(a[3]), "r"(b0), "r"(b1));
}

// smem tile geometry: 128 rows x 64 k (pair-interleaved), row stride 72 floats
#define TSTR 72
#define TILE_F (128 * TSTR)

// ---------------- K1: BMU GEMM via mma.sync tf32 (3-pass split) ------------
// block: 128 batch rows x 128 cells. 8 warps, each 16 batch rows x 128 cells.
// K=128 staged in two 64-chunks as (hi, lo) tf32 tiles.
// k layout within a group of 8: pos = 2*(k&3) + (k>>2)  -> (k, k+4) adjacent,
// so every mma fragment is a single LDS.64. Stride 72 => conflict-free.
__global__ __launch_bounds__(256, 1)
void k_bmu(const float* __restrict__ x, const float* __restrict__ w) {
    extern __shared__ float smem[];
    float* Xhi = smem;
    float* Xlo = smem + TILE_F;
    float* Whi = smem + 2 * TILE_F;
    float* Wlo = smem + 3 * TILE_F;
    float* w2s = smem + 4 * TILE_F;      // [128]

    const int tid  = threadIdx.x;
    const int wrp  = tid >> 5;
    const int lane = tid & 31;
    const int gid  = lane >> 2;          // group id 0..7
    const int tig  = lane & 3;           // thread in group
    const int b0 = blockIdx.x * 128;     // batch tile
    const int m0 = blockIdx.y * 128;     // cell tile

    // fold scratch zeroing into this kernel (completes before k_scatter)
    {
        int z = blockIdx.y * 16 + blockIdx.x;            // 0..127
        *(float4*)&g_S[z * 1024 + tid * 4] = make_float4(0.f, 0.f, 0.f, 0.f);
        if (tid < 2)
            *(float4*)&g_cnt[z * 8 + tid * 4] = make_float4(0.f, 0.f, 0.f, 0.f);
    }

    // w2 for this block's 128 cells (from global; L2-resident)
    if (tid < 128) {
        float s = 0.0f;
        #pragma unroll
        for (int g = 0; g < 32; g++) {
            float4 v = *(const float4*)&w[(m0 + tid) * DIM + g * 4];
            s += v.x * v.x + v.y * v.y + v.z * v.z + v.w * v.w;
        }
        w2s[tid] = s;
    }

    float acc[16][4];
    #pragma unroll
    for (int t = 0; t < 16; t++)
        #pragma unroll
        for (int j = 0; j < 4; j++) acc[t][j] = 0.0f;

    #pragma unroll 1
    for (int c = 0; c < 2; c++) {
        const int kc = c * 64;
        if (c) __syncthreads();   // protect tiles from re-staging while in use

        // stage chunk: split fp32 -> (hi, lo) tf32, pair-interleaved layout
        #pragma unroll
        for (int i = 0; i < 8; i++) {
            int idx = tid + i * 256;       // 0..2047
            int row = idx >> 4;            // 0..127
            int q   = idx & 15;            // float4 index; k = q*4..q*4+3
            int base = row * TSTR + (q >> 1) * 8 + (q & 1);
            float4 xv = *(const float4*)&x[(b0 + row) * DIM + kc + q * 4];
            float h;
            h = tf32_rna(xv.x); Xhi[base + 0] = h; Xlo[base + 0] = tf32_rna(xv.x - h);
            h = tf32_rna(xv.y); Xhi[base + 2] = h; Xlo[base + 2] = tf32_rna(xv.y - h);
            h = tf32_rna(xv.z); Xhi[base + 4] = h; Xlo[base + 4] = tf32_rna(xv.z - h);
            h = tf32_rna(xv.w); Xhi[base + 6] = h; Xlo[base + 6] = tf32_rna(xv.w - h);
            float4 wv = *(const float4*)&w[(m0 + row) * DIM + kc + q * 4];
            h = tf32_rna(wv.x); Whi[base + 0] = h; Wlo[base + 0] = tf32_rna(wv.x - h);
            h = tf32_rna(wv.y); Whi[base + 2] = h; Wlo[base + 2] = tf32_rna(wv.y - h);
            h = tf32_rna(wv.z); Whi[base + 4] = h; Wlo[base + 4] = tf32_rna(wv.z - h);
            h = tf32_rna(wv.w); Whi[base + 6] = h; Wlo[base + 6] = tf32_rna(wv.w - h);
        }
        __syncthreads();

        // 3 passes: hi*hi, hi*lo, lo*hi
        #pragma unroll
        for (int p = 0; p < 3; p++) {
            const float* At = (p == 2) ? Xlo : Xhi;
            const float* Bt = (p == 1) ? Wlo : Whi;
            #pragma unroll
            for (int g = 0; g < 8; g++) {
                const int apos = (wrp * 16 + gid) * TSTR + g * 8 + tig * 2;
                float2 av0 = *(const float2*)&At[apos];
                float2 av1 = *(const float2*)&At[apos + 8 * TSTR];
                uint32_t a[4];
                a[0] = __float_as_uint(av0.x);
                a[1] = __float_as_uint(av1.x);
                a[2] = __float_as_uint(av0.y);
                a[3] = __float_as_uint(av1.y);
                #pragma unroll
                for (int t = 0; t < 16; t++) {
                    const int bpos = (t * 8 + gid) * TSTR + g * 8 + tig * 2;
                    float2 bv = *(const float2*)&Bt[bpos];
                    mma_tf32(acc[t], a,
                             __float_as_uint(bv.x), __float_as_uint(bv.y));
                }
            }
        }
    }

    // epilogue: rows = batch, cols = cells -> per-thread argmin over 32 cols,
    // quad shuffle-min, lane tig==0 writes the row result.
    #pragma unroll
    for (int rp = 0; rp < 2; rp++) {       // row = gid, gid+8
        unsigned long long best = 0xFFFFFFFFFFFFFFFFULL;
        #pragma unroll
        for (int t = 0; t < 16; t++) {
            int c0 = t * 8 + tig * 2;
            float d2a = w2s[c0]     - 2.0f * acc[t][rp * 2 + 0];
            float d2b = w2s[c0 + 1] - 2.0f * acc[t][rp * 2 + 1];
            unsigned long long ka = ((unsigned long long)f2ord(d2a) << 32)
                                  | (unsigned long long)(m0 + c0);
            unsigned long long kb = ((unsigned long long)f2ord(d2b) << 32)
                                  | (unsigned long long)(m0 + c0 + 1);
            best = min(best, min(ka, kb));
        }
        best = min(best, __shfl_xor_sync(0xffffffffu, best, 1));
        best = min(best, __shfl_xor_sync(0xffffffffu, best, 2));
        if (tig == 0)
            g_part[blockIdx.y][b0 + wrp * 16 + gid + rp * 8] = best;
    }
}

// ---------------- K2: reduce partials + scatter x rows into BMU bins --------
__global__ void k_scatter(const float* __restrict__ x) {
    int warp = (blockIdx.x * blockDim.x + threadIdx.x) >> 5;  // 0..2047
    int lane = threadIdx.x & 31;
    if (warp >= BATCH) return;

    unsigned long long v = (lane < 8) ? g_part[lane][warp]
                                      : 0xFFFFFFFFFFFFFFFFULL;
    #pragma unroll
    for (int o = 4; o >= 1; o >>= 1)
        v = min(v, __shfl_xor_sync(0xffffffffu, v, o));
    v = __shfl_sync(0xffffffffu, v, 0);
    int m = (int)(v & 0xFFFFFFFFULL);

    float4 vv = *(const float4*)&x[warp * DIM + lane * 4];
    float* dst = &g_S[m * DIM + lane * 4];
    asm volatile("red.global.add.v4.f32 [%0], {%1, %2, %3, %4};"
                 :: "l"(dst), "f"(vv.x), "f"(vv.y), "f"(vv.z), "f"(vv.w)
                 : "memory");
    if (lane == 0) atomicAdd(&g_cnt[m], 1.0f);
}

// ---------------- K3: fused separable gaussian contraction + update ---------
// 128 blocks = (cx, d-quarter), 256 threads.
__global__ __launch_bounds__(256)
void k_tail(const float* __restrict__ w,
            const int* __restrict__ it,
            float* __restrict__ out) {
    __shared__ float4 Ts[32][9];     // [by][dq], padded
    __shared__ float tc_s[32];
    __shared__ float e_s[32];

    const int cx = blockIdx.x & 31;
    const int d0 = (blockIdx.x >> 5) * 32;   // d-quarter base
    const int tid = threadIdx.x;

    float lr_decay = 1.0f - (float)it[0] / NITER_F;
    float alpha_op = ALPHA_F * lr_decay;
    float sig = SIGMA_F * lr_decay;
    float inv_s2 = 1.0f / (sig * sig);

    if (tid < 32) e_s[tid] = expf(-(float)(tid * tid) * inv_s2);
    __syncthreads();

    // stage A: Ts[by][d] = sum_bx e(|cx-bx|) * S[by*32+bx][d]
    {
        const int by = tid >> 3;           // 0..31
        const int dq = tid & 7;            // float4 index
        const int d  = d0 + dq * 4;
        float4 a = make_float4(0.f, 0.f, 0.f, 0.f);
        #pragma unroll
        for (int bb = 0; bb < 4; bb++) {
            float4 sv[8];
            #pragma unroll
            for (int j = 0; j < 8; j++)
                sv[j] = *(const float4*)&g_S[(by * 32 + bb * 8 + j) * DIM + d];
            #pragma unroll
            for (int j = 0; j < 8; j++) {
                float e = e_s[abs(cx - (bb * 8 + j))];
                a.x += e * sv[j].x; a.y += e * sv[j].y;
                a.z += e * sv[j].z; a.w += e * sv[j].w;
            }
        }
        Ts[by][dq] = a;
    }
    if (tid < 32) {
        float c = 0.0f;
        #pragma unroll
        for (int bx = 0; bx < 32; bx++)
            c += e_s[abs(cx - bx)] * g_cnt[tid * 32 + bx];
        tc_s[tid] = c;
    }
    __syncthreads();

    // stage B
    {
        const int cy = tid >> 3;
        const int dq = tid & 7;
        const int d  = d0 + dq * 4;
        float4 a = make_float4(0.f, 0.f, 0.f, 0.f);
        float s = 0.0f;
        #pragma unroll
        for (int by = 0; by < 32; by++) {
            float e = e_s[abs(cy - by)];
            float4 t = Ts[by][dq];
            a.x += e * t.x; a.y += e * t.y;
            a.z += e * t.z; a.w += e * t.w;
            s += e * tc_s[by];
        }
        const int c = (cy * 32 + cx) * DIM + d;
        float4 wv = *(const float4*)&w[c];
        float4 o;
        o.x = wv.x + alpha_op * (a.x - s * wv.x);
        o.y = wv.y + alpha_op * (a.y - s * wv.y);
        o.z = wv.z + alpha_op * (a.z - s * wv.z);
        o.w = wv.w + alpha_op * (a.w - s * wv.w);
        *(float4*)&out[c] = o;
    }
}

// ---------------- launch ----------------
extern "C" void kernel_launch(void* const* d_in, const int* in_sizes, int n_in,
                              void* d_out, int out_size) {
    const float* x   = (const float*)d_in[0];   // [2048,128]
    const float* w   = (const float*)d_in[1];   // [1024,128]
    const int*   it  = (const int*)d_in[3];
    float* out = (float*)d_out;

    const int bmu_smem = 4 * TILE_F * 4 + 128 * 4;   // 147968 B
    cudaFuncSetAttribute(k_bmu, cudaFuncAttributeMaxDynamicSharedMemorySize,
                         bmu_smem);

    k_bmu<<<dim3(16, 8), 256, bmu_smem>>>(x, w);
    k_scatter<<<256, 256>>>(x);
    k_tail<<<128, 256>>>(w, it, out);
}

// round 12
// speedup vs baseline: 1.0387x; 1.0307x over previous
#include <cuda_runtime.h>
#include <cstdint>

#define MN       1024
#define BATCH    2048
#define DIM      128
#define NITER_F  100.0f
#define ALPHA_F  0.3f
#define SIGMA_F  16.0f

// ---------------- scratch ----------------
__device__ unsigned long long g_part[16][BATCH]; // per-cell-block argmin partials
__device__ float g_S[MN * DIM];
__device__ float g_cnt[MN];

__device__ __forceinline__ unsigned int f2ord(float f) {
    unsigned int u = __float_as_uint(f);
    return (u & 0x80000000u) ? ~u : (u | 0x80000000u);
}

__device__ __forceinline__ float tf32_rna(float v) {
    uint32_t u;
    asm("cvt.rna.tf32.f32 %0, %1;" : "=r"(u) : "f"(v));
    return __uint_as_float(u);
}

__device__ __forceinline__ void mma_tf32(float* d, const uint32_t* a,
                                         uint32_t b0, uint32_t b1) {
    asm volatile(
        "mma.sync.aligned.m16n8k8.row.col.f32.tf32.tf32.f32 "
        "{%0,%1,%2,%3}, {%4,%5,%6,%7}, {%8,%9}, {%0,%1,%2,%3};"
        : "+f"(d[0]), "+f"(d[1]), "+f"(d[2]), "+f"(d[3])
        : "r"(a[0]), "r"(a[1]), "r"(a[2]), "r"(a[3]), "r"(b0), "r"(b1));
}

// smem tile geometry: rows x 64 k (pair-interleaved), row stride 72 floats
#define TSTR 72
#define XTILE_F (128 * TSTR)     // X: 128 batch rows
#define WTILE_F (64 * TSTR)      // W: 64 cell rows

#define OFF_XHI 0
#define OFF_XLO (OFF_XHI + XTILE_F)
#define OFF_WHI (OFF_XLO + XTILE_F)
#define OFF_WLO (OFF_WHI + WTILE_F)
#define OFF_W2S (OFF_WLO + WTILE_F)
#define BMU_SMEM_F (OFF_W2S + 64)

// ---------------- K1: BMU GEMM via mma.sync tf32 (3-pass split) ------------
// block: 128 batch rows x 64 cells, 8 warps each 16 batch rows x 64 cells.
// 2 CTAs/SM (smem ~108KB, regs<=128) -> 4 warps/SMSP.
// k layout within a group of 8: pos = 2*(k&3) + (k>>2)  -> (k, k+4) adjacent,
// so every mma fragment is a single LDS.64. Stride 72 => conflict-free.
__global__ __launch_bounds__(256, 2)
void k_bmu(const float* __restrict__ x, const float* __restrict__ w) {
    extern __shared__ float smem[];
    float* w2s = smem + OFF_W2S;         // [64]

    const int tid  = threadIdx.x;
    const int wrp  = tid >> 5;
    const int lane = tid & 31;
    const int gid  = lane >> 2;          // group id 0..7
    const int tig  = lane & 3;           // thread in group
    const int b0 = blockIdx.x * 128;     // batch tile
    const int m0 = blockIdx.y * 64;      // cell tile

    // fold scratch zeroing into this kernel: 256 blocks x 512 floats = all g_S
    {
        int z = blockIdx.y * 16 + blockIdx.x;            // 0..255
        if (tid < 128)
            *(float4*)&g_S[z * 512 + tid * 4] = make_float4(0.f, 0.f, 0.f, 0.f);
        if (tid == 255)
            *(float4*)&g_cnt[z * 4] = make_float4(0.f, 0.f, 0.f, 0.f);
    }

    // w2 for this block's 64 cells (L2-resident)
    if (tid < 64) {
        float s = 0.0f;
        #pragma unroll
        for (int g = 0; g < 32; g++) {
            float4 v = *(const float4*)&w[(m0 + tid) * DIM + g * 4];
            s += v.x * v.x + v.y * v.y + v.z * v.z + v.w * v.w;
        }
        w2s[tid] = s;
    }

    float acc[8][4];
    #pragma unroll
    for (int t = 0; t < 8; t++)
        #pragma unroll
        for (int j = 0; j < 4; j++) acc[t][j] = 0.0f;

    #pragma unroll 1
    for (int c = 0; c < 2; c++) {
        const int kc = c * 64;
        if (c) __syncthreads();   // protect tiles while prior mma reads

        // stage X chunk: 128 rows x 16 q -> 2048 float4s, 8 per thread
        #pragma unroll
        for (int i = 0; i < 8; i++) {
            int idx = tid + i * 256;
            int row = idx >> 4;
            int q   = idx & 15;
            int base = row * TSTR + (q >> 1) * 8 + (q & 1);
            float4 xv = *(const float4*)&x[(b0 + row) * DIM + kc + q * 4];
            float h;
            h = tf32_rna(xv.x); smem[OFF_XHI + base + 0] = h; smem[OFF_XLO + base + 0] = tf32_rna(xv.x - h);
            h = tf32_rna(xv.y); smem[OFF_XHI + base + 2] = h; smem[OFF_XLO + base + 2] = tf32_rna(xv.y - h);
            h = tf32_rna(xv.z); smem[OFF_XHI + base + 4] = h; smem[OFF_XLO + base + 4] = tf32_rna(xv.z - h);
            h = tf32_rna(xv.w); smem[OFF_XHI + base + 6] = h; smem[OFF_XLO + base + 6] = tf32_rna(xv.w - h);
        }
        // stage W chunk: 64 rows x 16 q -> 1024 float4s, 4 per thread
        #pragma unroll
        for (int i = 0; i < 4; i++) {
            int idx = tid + i * 256;
            int row = idx >> 4;
            int q   = idx & 15;
            int base = row * TSTR + (q >> 1) * 8 + (q & 1);
            float4 wv = *(const float4*)&w[(m0 + row) * DIM + kc + q * 4];
            float h;
            h = tf32_rna(wv.x); smem[OFF_WHI + base + 0] = h; smem[OFF_WLO + base + 0] = tf32_rna(wv.x - h);
            h = tf32_rna(wv.y); smem[OFF_WHI + base + 2] = h; smem[OFF_WLO + base + 2] = tf32_rna(wv.y - h);
            h = tf32_rna(wv.z); smem[OFF_WHI + base + 4] = h; smem[OFF_WLO + base + 4] = tf32_rna(wv.z - h);
            h = tf32_rna(wv.w); smem[OFF_WHI + base + 6] = h; smem[OFF_WLO + base + 6] = tf32_rna(wv.w - h);
        }
        __syncthreads();

        // 3 passes: hi*hi, hi*lo, lo*hi
        #pragma unroll 1
        for (int p = 0; p < 3; p++) {
            const float* At = smem + ((p == 2) ? OFF_XLO : OFF_XHI);
            const float* Bt = smem + ((p == 1) ? OFF_WLO : OFF_WHI);
            #pragma unroll
            for (int g = 0; g < 8; g++) {
                const int apos = (wrp * 16 + gid) * TSTR + g * 8 + tig * 2;
                float2 av0 = *(const float2*)&At[apos];
                float2 av1 = *(const float2*)&At[apos + 8 * TSTR];
                uint32_t a[4];
                a[0] = __float_as_uint(av0.x);
                a[1] = __float_as_uint(av1.x);
                a[2] = __float_as_uint(av0.y);
                a[3] = __float_as_uint(av1.y);
                #pragma unroll
                for (int t = 0; t < 8; t++) {
                    const int bpos = (t * 8 + gid) * TSTR + g * 8 + tig * 2;
                    float2 bv = *(const float2*)&Bt[bpos];
                    mma_tf32(acc[t], a,
                             __float_as_uint(bv.x), __float_as_uint(bv.y));
                }
            }
        }
    }

    // epilogue: rows = batch, cols = cells -> per-thread argmin over 16 cols,
    // quad shuffle-min, lane tig==0 writes the row result.
    #pragma unroll
    for (int rp = 0; rp < 2; rp++) {       // row = gid, gid+8
        unsigned long long best = 0xFFFFFFFFFFFFFFFFULL;
        #pragma unroll
        for (int t = 0; t < 8; t++) {
            int c0 = t * 8 + tig * 2;
            float d2a = w2s[c0]     - 2.0f * acc[t][rp * 2 + 0];
            float d2b = w2s[c0 + 1] - 2.0f * acc[t][rp * 2 + 1];
            unsigned long long ka = ((unsigned long long)f2ord(d2a) << 32)
                                  | (unsigned long long)(m0 + c0);
            unsigned long long kb = ((unsigned long long)f2ord(d2b) << 32)
                                  | (unsigned long long)(m0 + c0 + 1);
            best = min(best, min(ka, kb));
        }
        best = min(best, __shfl_xor_sync(0xffffffffu, best, 1));
        best = min(best, __shfl_xor_sync(0xffffffffu, best, 2));
        if (tig == 0)
            g_part[blockIdx.y][b0 + wrp * 16 + gid + rp * 8] = best;
    }
}

// ---------------- K2: reduce partials + scatter x rows into BMU bins --------
__global__ void k_scatter(const float* __restrict__ x) {
    int warp = (blockIdx.x * blockDim.x + threadIdx.x) >> 5;  // 0..2047
    int lane = threadIdx.x & 31;
    if (warp >= BATCH) return;

    unsigned long long v = (lane < 16) ? g_part[lane][warp]
                                       : 0xFFFFFFFFFFFFFFFFULL;
    #pragma unroll
    for (int o = 8; o >= 1; o >>= 1)
        v = min(v, __shfl_xor_sync(0xffffffffu, v, o));
    v = __shfl_sync(0xffffffffu, v, 0);
    int m = (int)(v & 0xFFFFFFFFULL);

    float4 vv = *(const float4*)&x[warp * DIM + lane * 4];
    float* dst = &g_S[m * DIM + lane * 4];
    asm volatile("red.global.add.v4.f32 [%0], {%1, %2, %3, %4};"
                 :: "l"(dst), "f"(vv.x), "f"(vv.y), "f"(vv.z), "f"(vv.w)
                 : "memory");
    if (lane == 0) atomicAdd(&g_cnt[m], 1.0f);
}

// ---------------- K3: fused separable gaussian contraction + update ---------
// 128 blocks = (cx, d-quarter), 256 threads.
__global__ __launch_bounds__(256)
void k_tail(const float* __restrict__ w,
            const int* __restrict__ it,
            float* __restrict__ out) {
    __shared__ float4 Ts[32][9];     // [by][dq], padded
    __shared__ float tc_s[32];
    __shared__ float e_s[32];

    const int cx = blockIdx.x & 31;
    const int d0 = (blockIdx.x >> 5) * 32;   // d-quarter base
    const int tid = threadIdx.x;

    float lr_decay = 1.0f - (float)it[0] / NITER_F;
    float alpha_op = ALPHA_F * lr_decay;
    float sig = SIGMA_F * lr_decay;
    float inv_s2 = 1.0f / (sig * sig);

    if (tid < 32) e_s[tid] = expf(-(float)(tid * tid) * inv_s2);
    __syncthreads();

    // stage A: Ts[by][d] = sum_bx e(|cx-bx|) * S[by*32+bx][d]
    {
        const int by = tid >> 3;           // 0..31
        const int dq = tid & 7;            // float4 index
        const int d  = d0 + dq * 4;
        float4 a = make_float4(0.f, 0.f, 0.f, 0.f);
        #pragma unroll
        for (int bb = 0; bb < 4; bb++) {
            float4 sv[8];
            #pragma unroll
            for (int j = 0; j < 8; j++)
                sv[j] = *(const float4*)&g_S[(by * 32 + bb * 8 + j) * DIM + d];
            #pragma unroll
            for (int j = 0; j < 8; j++) {
                float e = e_s[abs(cx - (bb * 8 + j))];
                a.x += e * sv[j].x; a.y += e * sv[j].y;
                a.z += e * sv[j].z; a.w += e * sv[j].w;
            }
        }
        Ts[by][dq] = a;
    }
    if (tid < 32) {
        float c = 0.0f;
        #pragma unroll
        for (int bx = 0; bx < 32; bx++)
            c += e_s[abs(cx - bx)] * g_cnt[tid * 32 + bx];
        tc_s[tid] = c;
    }
    __syncthreads();

    // stage B
    {
        const int cy = tid >> 3;
        const int dq = tid & 7;
        const int d  = d0 + dq * 4;
        float4 a = make_float4(0.f, 0.f, 0.f, 0.f);
        float s = 0.0f;
        #pragma unroll
        for (int by = 0; by < 32; by++) {
            float e = e_s[abs(cy - by)];
            float4 t = Ts[by][dq];
            a.x += e * t.x; a.y += e * t.y;
            a.z += e * t.z; a.w += e * t.w;
            s += e * tc_s[by];
        }
        const int c = (cy * 32 + cx) * DIM + d;
        float4 wv = *(const float4*)&w[c];
        float4 o;
        o.x = wv.x + alpha_op * (a.x - s * wv.x);
        o.y = wv.y + alpha_op * (a.y - s * wv.y);
        o.z = wv.z + alpha_op * (a.z - s * wv.z);
        o.w = wv.w + alpha_op * (a.w - s * wv.w);
        *(float4*)&out[c] = o;
    }
}

// ---------------- launch ----------------
extern "C" void kernel_launch(void* const* d_in, const int* in_sizes, int n_in,
                              void* d_out, int out_size) {
    const float* x   = (const float*)d_in[0];   // [2048,128]
    const float* w   = (const float*)d_in[1];   // [1024,128]
    const int*   it  = (const int*)d_in[3];
    float* out = (float*)d_out;

    const int bmu_smem = BMU_SMEM_F * 4;   // ~110.5KB
    cudaFuncSetAttribute(k_bmu, cudaFuncAttributeMaxDynamicSharedMemorySize,
                         bmu_smem);

    k_bmu<<<dim3(16, 16), 256, bmu_smem>>>(x, w);
    k_scatter<<<256, 256>>>(x);
    k_tail<<<128, 256>>>(w, it, out);
}